// round 15
// baseline (speedup 1.0000x reference)
#include <cuda_runtime.h>
#include <cuda_fp16.h>
#include <math.h>
#include <stdint.h>

#define HIDDEN 1024
#define INTER  2816
#define NE     8
#define TOPK   2
#define NTASKEXP 4
#define NGEN   2
#define NTOK   8192
#define NPAIR  (NTOK*TOPK)
#define WELEM  (NE*INTER*HIDDEN)

#define BM 128
#define BN 64
#define BKH 64            // K halves per stage (128B row)
#define ROWB 144          // row stride bytes (128 data + 16 pad)
#define STG1 36864        // (128+64+64) rows * 144B
#define STG2 27648        // (128+64) rows * 144B
#define SMEM1 (3*STG1)    // 110592 -> 2 blocks/SM
#define SMEM2 (3*STG2)    // 82944  -> 2 blocks/SM

// ---- scratch (static device memory; no runtime allocation) ----
__device__ int    g_active[NE];
__device__ int    g_counts[NE];
__device__ int    g_offsets[NE];
__device__ int    g_cursor[NE];
__device__ int    g_pair_token[NPAIR];
__device__ float  g_pair_w[NPAIR];
__device__ int    g_tok_e[NTOK * TOPK];
__device__ float  g_tok_w[NTOK * TOPK];
__device__ __half g_act[(size_t)NPAIR * INTER];
__device__ __half g_hs_h[(size_t)NTOK * HIDDEN];
__device__ __half g_gp_h[(size_t)WELEM];
__device__ __half g_up_h[(size_t)WELEM];
__device__ __half g_dp_h[(size_t)WELEM];

// ---- streams/events (created once at static init; no device memory) ----
static cudaStream_t s_cvt, s_exp[4];
static cudaEvent_t  ev_route, ev_prep, ev_dp, ev_g2[4], ev_done[4];
namespace {
struct StreamInit {
    StreamInit() {
        cudaStreamCreateWithFlags(&s_cvt, cudaStreamNonBlocking);
        for (int i = 0; i < 4; i++)
            cudaStreamCreateWithFlags(&s_exp[i], cudaStreamNonBlocking);
        cudaEventCreateWithFlags(&ev_route, cudaEventDisableTiming);
        cudaEventCreateWithFlags(&ev_prep,  cudaEventDisableTiming);
        cudaEventCreateWithFlags(&ev_dp,    cudaEventDisableTiming);
        for (int i = 0; i < 4; i++) {
            cudaEventCreateWithFlags(&ev_g2[i], cudaEventDisableTiming);
            cudaEventCreateWithFlags(&ev_done[i], cudaEventDisableTiming);
        }
    }
};
static StreamInit s_stream_init;
}

// ---------------------------------------------------------------------------
__device__ __forceinline__ void cp16(void* smem_ptr, const void* gptr) {
    uint32_t s = (uint32_t)__cvta_generic_to_shared(smem_ptr);
    asm volatile("cp.async.cg.shared.global [%0], [%1], 16;\n" :: "r"(s), "l"(gptr));
}
__device__ __forceinline__ void cp_commit() { asm volatile("cp.async.commit_group;\n"); }
__device__ __forceinline__ void cp_wait0()  { asm volatile("cp.async.wait_group 0;\n" ::: "memory"); }
__device__ __forceinline__ void cp_wait1()  { asm volatile("cp.async.wait_group 1;\n" ::: "memory"); }

__device__ __forceinline__ uint32_t smem_u32(const void* p) {
    return (uint32_t)__cvta_generic_to_shared(p);
}
__device__ __forceinline__ void ldsm4(uint32_t* r, uint32_t addr) {
    asm volatile("ldmatrix.sync.aligned.m8n8.x4.shared.b16 {%0,%1,%2,%3}, [%4];"
                 : "=r"(r[0]), "=r"(r[1]), "=r"(r[2]), "=r"(r[3]) : "r"(addr));
}
__device__ __forceinline__ void mma_f16(float* c, const uint32_t* a, const uint32_t* b) {
    asm volatile(
        "mma.sync.aligned.m16n8k16.row.col.f32.f16.f16.f32 "
        "{%0,%1,%2,%3}, {%4,%5,%6,%7}, {%8,%9}, {%0,%1,%2,%3};"
        : "+f"(c[0]), "+f"(c[1]), "+f"(c[2]), "+f"(c[3])
        : "r"(a[0]), "r"(a[1]), "r"(a[2]), "r"(a[3]), "r"(b[0]), "r"(b[1]));
}

// ---------------------------------------------------------------------------
// K1: task routing + counter reset
// ---------------------------------------------------------------------------
__global__ void k_task_route(const float* __restrict__ task_emb,
                             const int* __restrict__ task_id_p,
                             const float* __restrict__ trw) {
    __shared__ float sc[NE];
    int tid  = threadIdx.x;
    int e    = tid / 32;
    int lane = tid % 32;
    const float* tv = task_emb + (size_t)task_id_p[0] * HIDDEN;
    float acc = 0.f;
    if (e < NE) {
        for (int d = lane; d < HIDDEN; d += 32)
            acc += trw[(size_t)e * HIDDEN + d] * tv[d];
        #pragma unroll
        for (int o = 16; o > 0; o >>= 1)
            acc += __shfl_xor_sync(0xFFFFFFFFu, acc, o);
        if (lane == 0) sc[e] = acc;
    }
    __syncthreads();
    if (tid == 0) {
        float s[NE]; bool act[NE];
        for (int i = 0; i < NE; i++) { s[i] = sc[i]; act[i] = false; }
        for (int k = 0; k < NTASKEXP; k++) {
            int best = 0; float bv = -1e30f;
            for (int i = 0; i < NE; i++)
                if (!act[i] && s[i] > bv) { bv = s[i]; best = i; }
            act[best] = true;
        }
        for (int i = NE - NGEN; i < NE; i++) act[i] = true;
        for (int i = 0; i < NE; i++) {
            g_active[i] = act[i] ? 1 : 0;
            g_counts[i] = 0;
            g_cursor[i] = 0;
        }
    }
}

// ---------------------------------------------------------------------------
// K2: token gating (exact fp32, gw cached in smem) + fp16 hs copy + zero out
// ---------------------------------------------------------------------------
__global__ void __launch_bounds__(256)
k_gate(const float* __restrict__ hs,
       const float* __restrict__ task_emb,
       const int* __restrict__ task_id_p,
       const float* __restrict__ gw,
       float* __restrict__ out) {
    __shared__ float4 s_gw[NE * HIDDEN / 4];   // 32 KB
    int tid = threadIdx.x;
    int wid = tid >> 5;
    int lane = tid & 31;
    int token = blockIdx.x * 8 + wid;

    #pragma unroll
    for (int t = 0; t < 8; t++)
        s_gw[tid + t * 256] = ((const float4*)gw)[tid + t * 256];

    float4* oz = (float4*)(out + (size_t)token * HIDDEN);
    #pragma unroll
    for (int t = 0; t < 8; t++)
        oz[lane + t * 32] = make_float4(0.f, 0.f, 0.f, 0.f);

    __syncthreads();

    const float4* tv4 = (const float4*)(task_emb + (size_t)task_id_p[0] * HIDDEN);
    const float4* h4  = (const float4*)(hs + (size_t)token * HIDDEN);
    uint2* ht4 = (uint2*)(g_hs_h + (size_t)token * HIDDEN);

    float acc[NE];
    #pragma unroll
    for (int e = 0; e < NE; e++) acc[e] = 0.f;

    #pragma unroll
    for (int it = 0; it < 8; it++) {
        int d4 = lane + it * 32;
        float4 hv = h4[d4];
        float4 tq = tv4[d4];
        __half2 lo = __floats2half2_rn(hv.x, hv.y);
        __half2 hi = __floats2half2_rn(hv.z, hv.w);
        uint2 o;
        o.x = *(const uint32_t*)&lo;
        o.y = *(const uint32_t*)&hi;
        ht4[d4] = o;
        float x0 = hv.x + tq.x, x1 = hv.y + tq.y, x2 = hv.z + tq.z, x3 = hv.w + tq.w;
        #pragma unroll
        for (int e = 0; e < NE; e++) {
            float4 wv = s_gw[e * (HIDDEN / 4) + d4];
            acc[e] += x0 * wv.x + x1 * wv.y + x2 * wv.z + x3 * wv.w;
        }
    }
    #pragma unroll
    for (int e = 0; e < NE; e++) {
        #pragma unroll
        for (int o = 16; o > 0; o >>= 1)
            acc[e] += __shfl_xor_sync(0xFFFFFFFFu, acc[e], o);
    }
    if (lane == 0) {
        float m = -1e30f;
        #pragma unroll
        for (int e = 0; e < NE; e++)
            if (g_active[e] && acc[e] > m) m = acc[e];
        float p[NE]; float Z = 0.f;
        #pragma unroll
        for (int e = 0; e < NE; e++) {
            p[e] = g_active[e] ? expf(acc[e] - m) : 0.f;
            Z += p[e];
        }
        float inv = 1.f / Z;
        int i0 = 0; float v0 = -1.f;
        #pragma unroll
        for (int e = 0; e < NE; e++) {
            float s = p[e] * inv;
            if (s > v0) { v0 = s; i0 = e; }
        }
        int i1 = -1; float v1 = -1.f;
        #pragma unroll
        for (int e = 0; e < NE; e++) {
            if (e == i0) continue;
            float s = p[e] * inv;
            if (s > v1) { v1 = s; i1 = e; }
        }
        float ws = v0 + v1 + 1e-6f;
        g_tok_e[token * 2 + 0] = i0;
        g_tok_e[token * 2 + 1] = i1;
        g_tok_w[token * 2 + 0] = v0 / ws;
        g_tok_w[token * 2 + 1] = v1 / ws;
        atomicAdd(&g_counts[i0], 1);
        atomicAdd(&g_counts[i1], 1);
    }
}

__global__ void k_prefix() {
    if (threadIdx.x == 0) {
        int o = 0;
        for (int e = 0; e < NE; e++) { g_offsets[e] = o; o += g_counts[e]; }
    }
}

__global__ void k_place() {
    int n = blockIdx.x * blockDim.x + threadIdx.x;
    if (n >= NTOK) return;
    #pragma unroll
    for (int k = 0; k < TOPK; k++) {
        int e = g_tok_e[n * 2 + k];
        int slot = atomicAdd(&g_cursor[e], 1);
        int idx = g_offsets[e] + slot;
        g_pair_token[idx] = n;
        g_pair_w[idx] = g_tok_w[n * 2 + k];
    }
}

// ---------------------------------------------------------------------------
// per-expert gate/up weight fp32 -> fp16 (active only); y selects tensor
// ---------------------------------------------------------------------------
__global__ void k_cvt_gu(const float4* __restrict__ gp, const float4* __restrict__ up,
                         uint4* __restrict__ gph, uint4* __restrict__ uph, int e) {
    if (!g_active[e]) return;
    const int n8 = INTER * HIDDEN / 8;
    const float4* in = (blockIdx.y == 0) ? gp : up;
    uint4* out = (blockIdx.y == 0) ? gph : uph;
    const float4* src = in + (size_t)e * n8 * 2;
    uint4* dst = out + (size_t)e * n8;
    for (int i = blockIdx.x * blockDim.x + threadIdx.x; i < n8; i += gridDim.x * blockDim.x) {
        float4 v0 = src[i * 2 + 0];
        float4 v1 = src[i * 2 + 1];
        __half2 a = __floats2half2_rn(v0.x, v0.y);
        __half2 b = __floats2half2_rn(v0.z, v0.w);
        __half2 c = __floats2half2_rn(v1.x, v1.y);
        __half2 d = __floats2half2_rn(v1.z, v1.w);
        uint4 o;
        o.x = *(const uint32_t*)&a;
        o.y = *(const uint32_t*)&b;
        o.z = *(const uint32_t*)&c;
        o.w = *(const uint32_t*)&d;
        dst[i] = o;
    }
}

// down-proj fp32 -> fp16, all experts (active only); hidden under ffn1
__global__ void k_cvt_dp(const float4* __restrict__ dp, uint4* __restrict__ dph) {
    int e = blockIdx.y;
    if (!g_active[e]) return;
    const int n8 = INTER * HIDDEN / 8;
    const float4* src = dp + (size_t)e * n8 * 2;
    uint4* dst = dph + (size_t)e * n8;
    for (int i = blockIdx.x * blockDim.x + threadIdx.x; i < n8; i += gridDim.x * blockDim.x) {
        float4 v0 = src[i * 2 + 0];
        float4 v1 = src[i * 2 + 1];
        __half2 a = __floats2half2_rn(v0.x, v0.y);
        __half2 b = __floats2half2_rn(v0.z, v0.w);
        __half2 c = __floats2half2_rn(v1.x, v1.y);
        __half2 d = __floats2half2_rn(v1.z, v1.w);
        uint4 o;
        o.x = *(const uint32_t*)&a;
        o.y = *(const uint32_t*)&b;
        o.z = *(const uint32_t*)&c;
        o.w = *(const uint32_t*)&d;
        dst[i] = o;
    }
}

// ---------------------------------------------------------------------------
// K5: GEMM1 (gate & up fused) + SwiGLU. BK=64, 3-stage, 2 blocks/SM.
// ---------------------------------------------------------------------------
__global__ void __launch_bounds__(256, 2)
k_ffn1(int e) {
    extern __shared__ __align__(16) char sm[];
    int cnt  = g_counts[e];
    int moff = blockIdx.x * BM;
    if (moff >= cnt) return;
    int off = g_offsets[e];
    int n0  = blockIdx.y * BN;
    int tid = threadIdx.x;

    int c16 = tid & 7;
    int rb  = tid >> 3;
    const char* srcA[4];
    uint32_t dA[4];
    #pragma unroll
    for (int t = 0; t < 4; t++) {
        int row = rb + 32 * t;
        dA[t] = (uint32_t)row * ROWB + c16 * 16u;
        int r = moff + row; if (r > cnt - 1) r = cnt - 1;
        srcA[t] = (const char*)(g_hs_h + (size_t)g_pair_token[off + r] * HIDDEN) + c16 * 16;
    }
    const char* srcG = (const char*)(g_gp_h + (size_t)e * INTER * HIDDEN +
                                     (size_t)(n0 + rb) * HIDDEN) + c16 * 16;
    const char* srcU = (const char*)(g_up_h + (size_t)e * INTER * HIDDEN +
                                     (size_t)(n0 + rb) * HIDDEN) + c16 * 16;
    const uint32_t dG = 18432u + (uint32_t)rb * ROWB + c16 * 16u;
    const uint32_t dU = 27648u + (uint32_t)rb * ROWB + c16 * 16u;
    const size_t BROW32 = (size_t)32 * HIDDEN * 2;

    #pragma unroll
    for (int s = 0; s < 2; s++) {
        char* st = sm + s * STG1;
        int adv = s * 128;
        #pragma unroll
        for (int t = 0; t < 4; t++) cp16(st + dA[t], srcA[t] + adv);
        cp16(st + dG, srcG + adv); cp16(st + dG + 32 * ROWB, srcG + BROW32 + adv);
        cp16(st + dU, srcU + adv); cp16(st + dU + 32 * ROWB, srcU + BROW32 + adv);
        cp_commit();
    }

    uint32_t sb = smem_u32(sm);
    int w = tid >> 5, lane = tid & 31;
    int wm = w >> 1, wn = w & 1;
    uint32_t aoff = (uint32_t)(wm * 32 + (lane & 15)) * ROWB + (lane >> 4) * 16u;
    uint32_t boff = (uint32_t)(wn * 32 + (lane & 7) + ((lane >> 4) << 3)) * ROWB
                    + ((lane >> 3) & 1) * 16u;

    float accg[2][4][4], accu[2][4][4];
    #pragma unroll
    for (int mt = 0; mt < 2; mt++)
        #pragma unroll
        for (int nt = 0; nt < 4; nt++)
            #pragma unroll
            for (int q = 0; q < 4; q++) { accg[mt][nt][q] = 0.f; accu[mt][nt][q] = 0.f; }

    const int T = HIDDEN / BKH;  // 16
    for (int j = 0; j < T; j++) {
        if (j < T - 1) cp_wait1(); else cp_wait0();
        __syncthreads();
        if (j + 2 < T) {
            char* st = sm + ((j + 2) % 3) * STG1;
            int adv = (j + 2) * 128;
            #pragma unroll
            for (int t = 0; t < 4; t++) cp16(st + dA[t], srcA[t] + adv);
            cp16(st + dG, srcG + adv); cp16(st + dG + 32 * ROWB, srcG + BROW32 + adv);
            cp16(st + dU, srcU + adv); cp16(st + dU + 32 * ROWB, srcU + BROW32 + adv);
            cp_commit();
        }
        uint32_t base = sb + (uint32_t)(j % 3) * STG1;
        #pragma unroll
        for (int kk = 0; kk < 4; kk++) {
            uint32_t a[2][4], bg[2][4], bu[2][4];
            ldsm4(a[0], base + aoff + kk * 32);
            ldsm4(a[1], base + aoff + 16 * ROWB + kk * 32);
            ldsm4(bg[0], base + 18432 + boff + kk * 32);
            ldsm4(bg[1], base + 18432 + boff + 16 * ROWB + kk * 32);
            ldsm4(bu[0], base + 27648 + boff + kk * 32);
            ldsm4(bu[1], base + 27648 + boff + 16 * ROWB + kk * 32);
            #pragma unroll
            for (int mt = 0; mt < 2; mt++)
                #pragma unroll
                for (int ng = 0; ng < 2; ng++)
                    #pragma unroll
                    for (int hh = 0; hh < 2; hh++) {
                        mma_f16(accg[mt][ng * 2 + hh], a[mt], &bg[ng][hh * 2]);
                        mma_f16(accu[mt][ng * 2 + hh], a[mt], &bu[ng][hh * 2]);
                    }
        }
    }

    #pragma unroll
    for (int mt = 0; mt < 2; mt++) {
        #pragma unroll
        for (int nt = 0; nt < 4; nt++) {
            int r0 = moff + wm * 32 + mt * 16 + (lane >> 2);
            int c  = n0 + wn * 32 + nt * 8 + 2 * (lane & 3);
            if (r0 < cnt) {
                __half* dst = g_act + (size_t)(off + r0) * INTER + c;
                float g0 = accg[mt][nt][0], u0 = accu[mt][nt][0];
                float g1 = accg[mt][nt][1], u1 = accu[mt][nt][1];
                *(__half2*)dst = __floats2half2_rn((g0 / (1.f + __expf(-g0))) * u0,
                                                   (g1 / (1.f + __expf(-g1))) * u1);
            }
            int r1 = r0 + 8;
            if (r1 < cnt) {
                __half* dst = g_act + (size_t)(off + r1) * INTER + c;
                float g0 = accg[mt][nt][2], u0 = accu[mt][nt][2];
                float g1 = accg[mt][nt][3], u1 = accu[mt][nt][3];
                *(__half2*)dst = __floats2half2_rn((g0 / (1.f + __expf(-g0))) * u0,
                                                   (g1 / (1.f + __expf(-g1))) * u1);
            }
        }
    }
}

// ---------------------------------------------------------------------------
// K6: GEMM2 (down) + fused weighted combine via atomicAdd.
// ---------------------------------------------------------------------------
__global__ void __launch_bounds__(256, 2)
k_ffn2(float* __restrict__ out, int e) {
    extern __shared__ __align__(16) char sm[];
    int cnt  = g_counts[e];
    int moff = blockIdx.x * BM;
    if (moff >= cnt) return;
    int off = g_offsets[e];
    int n0  = blockIdx.y * BN;
    int tid = threadIdx.x;

    int c16 = tid & 7;
    int rb  = tid >> 3;
    const char* srcA[4];
    uint32_t dA[4];
    #pragma unroll
    for (int t = 0; t < 4; t++) {
        int row = rb + 32 * t;
        dA[t] = (uint32_t)row * ROWB + c16 * 16u;
        int r = moff + row; if (r > cnt - 1) r = cnt - 1;
        srcA[t] = (const char*)(g_act + (size_t)(off + r) * INTER) + c16 * 16;
    }
    const char* srcB = (const char*)(g_dp_h + (size_t)e * HIDDEN * INTER +
                                     (size_t)(n0 + rb) * INTER) + c16 * 16;
    const uint32_t dB = 18432u + (uint32_t)rb * ROWB + c16 * 16u;
    const size_t BROW32 = (size_t)32 * INTER * 2;

    #pragma unroll
    for (int s = 0; s < 2; s++) {
        char* st = sm + s * STG2;
        int adv = s * 128;
        #pragma unroll
        for (int t = 0; t < 4; t++) cp16(st + dA[t], srcA[t] + adv);
        cp16(st + dB, srcB + adv); cp16(st + dB + 32 * ROWB, srcB + BROW32 + adv);
        cp_commit();
    }

    uint32_t sb = smem_u32(sm);
    int w = tid >> 5, lane = tid & 31;
    int wm = w >> 1, wn = w & 1;
    uint32_t aoff = (uint32_t)(wm * 32 + (lane & 15)) * ROWB + (lane >> 4) * 16u;
    uint32_t boff = (uint32_t)(wn * 32 + (lane & 7) + ((lane >> 4) << 3)) * ROWB
                    + ((lane >> 3) & 1) * 16u;

    float acc[2][4][4];
    #pragma unroll
    for (int mt = 0; mt < 2; mt++)
        #pragma unroll
        for (int nt = 0; nt < 4; nt++)
            #pragma unroll
            for (int q = 0; q < 4; q++) acc[mt][nt][q] = 0.f;

    const int T = INTER / BKH;  // 44
    for (int j = 0; j < T; j++) {
        if (j < T - 1) cp_wait1(); else cp_wait0();
        __syncthreads();
        if (j + 2 < T) {
            char* st = sm + ((j + 2) % 3) * STG2;
            int adv = (j + 2) * 128;
            #pragma unroll
            for (int t = 0; t < 4; t++) cp16(st + dA[t], srcA[t] + adv);
            cp16(st + dB, srcB + adv); cp16(st + dB + 32 * ROWB, srcB + BROW32 + adv);
            cp_commit();
        }
        uint32_t base = sb + (uint32_t)(j % 3) * STG2;
        #pragma unroll
        for (int kk = 0; kk < 4; kk++) {
            uint32_t a[2][4], bb[2][4];
            ldsm4(a[0], base + aoff + kk * 32);
            ldsm4(a[1], base + aoff + 16 * ROWB + kk * 32);
            ldsm4(bb[0], base + 18432 + boff + kk * 32);
            ldsm4(bb[1], base + 18432 + boff + 16 * ROWB + kk * 32);
            #pragma unroll
            for (int mt = 0; mt < 2; mt++)
                #pragma unroll
                for (int ng = 0; ng < 2; ng++)
                    #pragma unroll
                    for (int hh = 0; hh < 2; hh++)
                        mma_f16(acc[mt][ng * 2 + hh], a[mt], &bb[ng][hh * 2]);
        }
    }

    #pragma unroll
    for (int mt = 0; mt < 2; mt++) {
        int r0 = moff + wm * 32 + mt * 16 + (lane >> 2);
        int r1 = r0 + 8;
        int   t0 = 0, t1 = 0;
        float w0 = 0.f, w1 = 0.f;
        bool ok0 = r0 < cnt, ok1 = r1 < cnt;
        if (ok0) { t0 = g_pair_token[off + r0]; w0 = g_pair_w[off + r0]; }
        if (ok1) { t1 = g_pair_token[off + r1]; w1 = g_pair_w[off + r1]; }
        #pragma unroll
        for (int nt = 0; nt < 4; nt++) {
            int c = n0 + wn * 32 + nt * 8 + 2 * (lane & 3);
            if (ok0) {
                float* dst = out + (size_t)t0 * HIDDEN + c;
                atomicAdd(dst + 0, w0 * acc[mt][nt][0]);
                atomicAdd(dst + 1, w0 * acc[mt][nt][1]);
            }
            if (ok1) {
                float* dst = out + (size_t)t1 * HIDDEN + c;
                atomicAdd(dst + 0, w1 * acc[mt][nt][2]);
                atomicAdd(dst + 1, w1 * acc[mt][nt][3]);
            }
        }
    }
}

// ---------------------------------------------------------------------------
extern "C" void kernel_launch(void* const* d_in, const int* in_sizes, int n_in,
                              void* d_out, int out_size) {
    const float* hs   = (const float*)d_in[0];
    const int*   tid  = (const int*)d_in[1];
    const float* temb = (const float*)d_in[2];
    const float* trw  = (const float*)d_in[3];
    const float* gw   = (const float*)d_in[4];
    const float* gp   = (const float*)d_in[5];
    const float* up   = (const float*)d_in[6];
    const float* dp   = (const float*)d_in[7];
    float* out = (float*)d_out;

    cudaFuncSetAttribute(k_ffn1, cudaFuncAttributeMaxDynamicSharedMemorySize, SMEM1);
    cudaFuncSetAttribute(k_ffn2, cudaFuncAttributeMaxDynamicSharedMemorySize, SMEM2);

    __half* gph; __half* uph; __half* dph;
    cudaGetSymbolAddress((void**)&gph, g_gp_h);
    cudaGetSymbolAddress((void**)&uph, g_up_h);
    cudaGetSymbolAddress((void**)&dph, g_dp_h);

    // route on default stream; everything depends on it
    k_task_route<<<1, 256>>>(temb, tid, trw);
    cudaEventRecord(ev_route, 0);

    // gating chain on default stream (concurrent with gu cvts)
    k_gate<<<NTOK / 8, 256>>>(hs, temb, tid, gw, out);
    k_prefix<<<1, 32>>>();
    k_place<<<NTOK / 256, 256>>>();
    cudaEventRecord(ev_prep, 0);

    dim3 gcu(256, 2);                 // per-expert gu cvt: 2 tensors
    dim3 gdp(256, NE);                // dp cvt: all experts
    dim3 g1(NTOK / BM, INTER / BN);   // 64 x 44
    dim3 g2(NTOK / BM, HIDDEN / BN);  // 64 x 16

    // side stream: gu for experts 4..7 (per-expert events), then dp (hidden)
    cudaStreamWaitEvent(s_cvt, ev_route, 0);
    for (int e = 4; e < 8; e++) {
        k_cvt_gu<<<gcu, 256, 0, s_cvt>>>((const float4*)gp, (const float4*)up,
                                         (uint4*)gph, (uint4*)uph, e);
        cudaEventRecord(ev_g2[e - 4], s_cvt);
    }
    k_cvt_dp<<<gdp, 256, 0, s_cvt>>>((const float4*)dp, (uint4*)dph);
    cudaEventRecord(ev_dp, s_cvt);

    // per-expert chains: stream i handles experts i and i+4
    for (int i = 0; i < 4; i++) {
        cudaStreamWaitEvent(s_exp[i], ev_route, 0);
        k_cvt_gu<<<gcu, 256, 0, s_exp[i]>>>((const float4*)gp, (const float4*)up,
                                            (uint4*)gph, (uint4*)uph, i);
        cudaStreamWaitEvent(s_exp[i], ev_prep, 0);
        k_ffn1<<<g1, 256, SMEM1, s_exp[i]>>>(i);
        cudaStreamWaitEvent(s_exp[i], ev_dp, 0);
        k_ffn2<<<g2, 256, SMEM2, s_exp[i]>>>(out, i);
        cudaStreamWaitEvent(s_exp[i], ev_g2[i], 0);
        k_ffn1<<<g1, 256, SMEM1, s_exp[i]>>>(i + 4);
        k_ffn2<<<g2, 256, SMEM2, s_exp[i]>>>(out, i + 4);
        cudaEventRecord(ev_done[i], s_exp[i]);
    }
    for (int i = 0; i < 4; i++)
        cudaStreamWaitEvent(0, ev_done[i], 0);
}

// round 16
// speedup vs baseline: 1.0186x; 1.0186x over previous
#include <cuda_runtime.h>
#include <cuda_fp16.h>
#include <math.h>
#include <stdint.h>

#define HIDDEN 1024
#define INTER  2816
#define NE     8
#define TOPK   2
#define NTASKEXP 4
#define NGEN   2
#define NTOK   8192
#define NPAIR  (NTOK*TOPK)
#define WELEM  (NE*INTER*HIDDEN)

#define BM 128
#define BN 64
#define BKH 64            // K halves per stage (128B row)
#define ROWB 144          // row stride bytes (128 data + 16 pad)
#define STG1 36864        // (128+64+64) rows * 144B
#define STG2 27648        // (128+64) rows * 144B
#define SMEM1 (3*STG1)    // 110592 -> 2 blocks/SM
#define SMEM2 (4*STG2)    // 110592 -> 2 blocks/SM (4-stage)

// ---- scratch (static device memory; no runtime allocation) ----
__device__ int    g_active[NE];
__device__ int    g_counts[NE];
__device__ int    g_offsets[NE];
__device__ int    g_cursor[NE];
__device__ int    g_pair_token[NPAIR];
__device__ float  g_pair_w[NPAIR];
__device__ int    g_tok_e[NTOK * TOPK];
__device__ float  g_tok_w[NTOK * TOPK];
__device__ __half g_act[(size_t)NPAIR * INTER];
__device__ __half g_hs_h[(size_t)NTOK * HIDDEN];
__device__ __half g_gp_h[(size_t)WELEM];
__device__ __half g_up_h[(size_t)WELEM];
__device__ __half g_dp_h[(size_t)WELEM];

// ---- streams/events (created once at static init; no device memory) ----
static cudaStream_t s_cvt, s_exp[4];
static cudaEvent_t  ev_route, ev_cvt, ev_prep, ev_done[4];
namespace {
struct StreamInit {
    StreamInit() {
        cudaStreamCreateWithFlags(&s_cvt, cudaStreamNonBlocking);
        for (int i = 0; i < 4; i++)
            cudaStreamCreateWithFlags(&s_exp[i], cudaStreamNonBlocking);
        cudaEventCreateWithFlags(&ev_route, cudaEventDisableTiming);
        cudaEventCreateWithFlags(&ev_cvt,   cudaEventDisableTiming);
        cudaEventCreateWithFlags(&ev_prep,  cudaEventDisableTiming);
        for (int i = 0; i < 4; i++)
            cudaEventCreateWithFlags(&ev_done[i], cudaEventDisableTiming);
    }
};
static StreamInit s_stream_init;
}

// ---------------------------------------------------------------------------
__device__ __forceinline__ void cp16(void* smem_ptr, const void* gptr) {
    uint32_t s = (uint32_t)__cvta_generic_to_shared(smem_ptr);
    asm volatile("cp.async.cg.shared.global [%0], [%1], 16;\n" :: "r"(s), "l"(gptr));
}
__device__ __forceinline__ void cp_commit() { asm volatile("cp.async.commit_group;\n"); }
__device__ __forceinline__ void cp_wait0()  { asm volatile("cp.async.wait_group 0;\n" ::: "memory"); }
__device__ __forceinline__ void cp_wait1()  { asm volatile("cp.async.wait_group 1;\n" ::: "memory"); }
__device__ __forceinline__ void cp_wait2()  { asm volatile("cp.async.wait_group 2;\n" ::: "memory"); }

__device__ __forceinline__ uint32_t smem_u32(const void* p) {
    return (uint32_t)__cvta_generic_to_shared(p);
}
__device__ __forceinline__ void ldsm4(uint32_t* r, uint32_t addr) {
    asm volatile("ldmatrix.sync.aligned.m8n8.x4.shared.b16 {%0,%1,%2,%3}, [%4];"
                 : "=r"(r[0]), "=r"(r[1]), "=r"(r[2]), "=r"(r[3]) : "r"(addr));
}
__device__ __forceinline__ void mma_f16(float* c, const uint32_t* a, const uint32_t* b) {
    asm volatile(
        "mma.sync.aligned.m16n8k16.row.col.f32.f16.f16.f32 "
        "{%0,%1,%2,%3}, {%4,%5,%6,%7}, {%8,%9}, {%0,%1,%2,%3};"
        : "+f"(c[0]), "+f"(c[1]), "+f"(c[2]), "+f"(c[3])
        : "r"(a[0]), "r"(a[1]), "r"(a[2]), "r"(a[3]), "r"(b[0]), "r"(b[1]));
}

// ---------------------------------------------------------------------------
// K1: task routing + counter reset
// ---------------------------------------------------------------------------
__global__ void k_task_route(const float* __restrict__ task_emb,
                             const int* __restrict__ task_id_p,
                             const float* __restrict__ trw) {
    __shared__ float sc[NE];
    int tid  = threadIdx.x;
    int e    = tid / 32;
    int lane = tid % 32;
    const float* tv = task_emb + (size_t)task_id_p[0] * HIDDEN;
    float acc = 0.f;
    if (e < NE) {
        for (int d = lane; d < HIDDEN; d += 32)
            acc += trw[(size_t)e * HIDDEN + d] * tv[d];
        #pragma unroll
        for (int o = 16; o > 0; o >>= 1)
            acc += __shfl_xor_sync(0xFFFFFFFFu, acc, o);
        if (lane == 0) sc[e] = acc;
    }
    __syncthreads();
    if (tid == 0) {
        float s[NE]; bool act[NE];
        for (int i = 0; i < NE; i++) { s[i] = sc[i]; act[i] = false; }
        for (int k = 0; k < NTASKEXP; k++) {
            int best = 0; float bv = -1e30f;
            for (int i = 0; i < NE; i++)
                if (!act[i] && s[i] > bv) { bv = s[i]; best = i; }
            act[best] = true;
        }
        for (int i = NE - NGEN; i < NE; i++) act[i] = true;
        for (int i = 0; i < NE; i++) {
            g_active[i] = act[i] ? 1 : 0;
            g_counts[i] = 0;
            g_cursor[i] = 0;
        }
    }
}

// ---------------------------------------------------------------------------
// K2: token gating (exact fp32, gw cached in smem) + fp16 hs copy + zero out
// ---------------------------------------------------------------------------
__global__ void __launch_bounds__(256)
k_gate(const float* __restrict__ hs,
       const float* __restrict__ task_emb,
       const int* __restrict__ task_id_p,
       const float* __restrict__ gw,
       float* __restrict__ out) {
    __shared__ float4 s_gw[NE * HIDDEN / 4];   // 32 KB
    int tid = threadIdx.x;
    int wid = tid >> 5;
    int lane = tid & 31;
    int token = blockIdx.x * 8 + wid;

    #pragma unroll
    for (int t = 0; t < 8; t++)
        s_gw[tid + t * 256] = ((const float4*)gw)[tid + t * 256];

    float4* oz = (float4*)(out + (size_t)token * HIDDEN);
    #pragma unroll
    for (int t = 0; t < 8; t++)
        oz[lane + t * 32] = make_float4(0.f, 0.f, 0.f, 0.f);

    __syncthreads();

    const float4* tv4 = (const float4*)(task_emb + (size_t)task_id_p[0] * HIDDEN);
    const float4* h4  = (const float4*)(hs + (size_t)token * HIDDEN);
    uint2* ht4 = (uint2*)(g_hs_h + (size_t)token * HIDDEN);

    float acc[NE];
    #pragma unroll
    for (int e = 0; e < NE; e++) acc[e] = 0.f;

    #pragma unroll
    for (int it = 0; it < 8; it++) {
        int d4 = lane + it * 32;
        float4 hv = h4[d4];
        float4 tq = tv4[d4];
        __half2 lo = __floats2half2_rn(hv.x, hv.y);
        __half2 hi = __floats2half2_rn(hv.z, hv.w);
        uint2 o;
        o.x = *(const uint32_t*)&lo;
        o.y = *(const uint32_t*)&hi;
        ht4[d4] = o;
        float x0 = hv.x + tq.x, x1 = hv.y + tq.y, x2 = hv.z + tq.z, x3 = hv.w + tq.w;
        #pragma unroll
        for (int e = 0; e < NE; e++) {
            float4 wv = s_gw[e * (HIDDEN / 4) + d4];
            acc[e] += x0 * wv.x + x1 * wv.y + x2 * wv.z + x3 * wv.w;
        }
    }
    #pragma unroll
    for (int e = 0; e < NE; e++) {
        #pragma unroll
        for (int o = 16; o > 0; o >>= 1)
            acc[e] += __shfl_xor_sync(0xFFFFFFFFu, acc[e], o);
    }
    if (lane == 0) {
        float m = -1e30f;
        #pragma unroll
        for (int e = 0; e < NE; e++)
            if (g_active[e] && acc[e] > m) m = acc[e];
        float p[NE]; float Z = 0.f;
        #pragma unroll
        for (int e = 0; e < NE; e++) {
            p[e] = g_active[e] ? expf(acc[e] - m) : 0.f;
            Z += p[e];
        }
        float inv = 1.f / Z;
        int i0 = 0; float v0 = -1.f;
        #pragma unroll
        for (int e = 0; e < NE; e++) {
            float s = p[e] * inv;
            if (s > v0) { v0 = s; i0 = e; }
        }
        int i1 = -1; float v1 = -1.f;
        #pragma unroll
        for (int e = 0; e < NE; e++) {
            if (e == i0) continue;
            float s = p[e] * inv;
            if (s > v1) { v1 = s; i1 = e; }
        }
        float ws = v0 + v1 + 1e-6f;
        g_tok_e[token * 2 + 0] = i0;
        g_tok_e[token * 2 + 1] = i1;
        g_tok_w[token * 2 + 0] = v0 / ws;
        g_tok_w[token * 2 + 1] = v1 / ws;
        atomicAdd(&g_counts[i0], 1);
        atomicAdd(&g_counts[i1], 1);
    }
}

__global__ void k_prefix() {
    if (threadIdx.x == 0) {
        int o = 0;
        for (int e = 0; e < NE; e++) { g_offsets[e] = o; o += g_counts[e]; }
    }
}

__global__ void k_place() {
    int n = blockIdx.x * blockDim.x + threadIdx.x;
    if (n >= NTOK) return;
    #pragma unroll
    for (int k = 0; k < TOPK; k++) {
        int e = g_tok_e[n * 2 + k];
        int slot = atomicAdd(&g_cursor[e], 1);
        int idx = g_offsets[e] + slot;
        g_pair_token[idx] = n;
        g_pair_w[idx] = g_tok_w[n * 2 + k];
    }
}

// ---------------------------------------------------------------------------
// per-expert weight fp32 -> fp16 (gp, up, dp for one expert; active only)
// ---------------------------------------------------------------------------
__global__ void k_cvt_e(const float4* __restrict__ gp, const float4* __restrict__ up,
                        const float4* __restrict__ dp,
                        uint4* __restrict__ gph, uint4* __restrict__ uph,
                        uint4* __restrict__ dph, int e) {
    if (!g_active[e]) return;
    const int n8 = INTER * HIDDEN / 8;
    const float4* in = (blockIdx.y == 0) ? gp : (blockIdx.y == 1) ? up : dp;
    uint4* out = (blockIdx.y == 0) ? gph : (blockIdx.y == 1) ? uph : dph;
    const float4* src = in + (size_t)e * n8 * 2;
    uint4* dst = out + (size_t)e * n8;
    for (int i = blockIdx.x * blockDim.x + threadIdx.x; i < n8; i += gridDim.x * blockDim.x) {
        float4 v0 = src[i * 2 + 0];
        float4 v1 = src[i * 2 + 1];
        __half2 a = __floats2half2_rn(v0.x, v0.y);
        __half2 b = __floats2half2_rn(v0.z, v0.w);
        __half2 c = __floats2half2_rn(v1.x, v1.y);
        __half2 d = __floats2half2_rn(v1.z, v1.w);
        uint4 o;
        o.x = *(const uint32_t*)&a;
        o.y = *(const uint32_t*)&b;
        o.z = *(const uint32_t*)&c;
        o.w = *(const uint32_t*)&d;
        dst[i] = o;
    }
}

// ---------------------------------------------------------------------------
// K5: GEMM1 (gate & up fused) + SwiGLU. BK=64, 3-stage, 2 blocks/SM.
// ---------------------------------------------------------------------------
__global__ void __launch_bounds__(256, 2)
k_ffn1(int e) {
    extern __shared__ __align__(16) char sm[];
    int cnt  = g_counts[e];
    int moff = blockIdx.x * BM;
    if (moff >= cnt) return;
    int off = g_offsets[e];
    int n0  = blockIdx.y * BN;
    int tid = threadIdx.x;

    int c16 = tid & 7;
    int rb  = tid >> 3;
    const char* srcA[4];
    uint32_t dA[4];
    #pragma unroll
    for (int t = 0; t < 4; t++) {
        int row = rb + 32 * t;
        dA[t] = (uint32_t)row * ROWB + c16 * 16u;
        int r = moff + row; if (r > cnt - 1) r = cnt - 1;
        srcA[t] = (const char*)(g_hs_h + (size_t)g_pair_token[off + r] * HIDDEN) + c16 * 16;
    }
    const char* srcG = (const char*)(g_gp_h + (size_t)e * INTER * HIDDEN +
                                     (size_t)(n0 + rb) * HIDDEN) + c16 * 16;
    const char* srcU = (const char*)(g_up_h + (size_t)e * INTER * HIDDEN +
                                     (size_t)(n0 + rb) * HIDDEN) + c16 * 16;
    const uint32_t dG = 18432u + (uint32_t)rb * ROWB + c16 * 16u;
    const uint32_t dU = 27648u + (uint32_t)rb * ROWB + c16 * 16u;
    const size_t BROW32 = (size_t)32 * HIDDEN * 2;

    #pragma unroll
    for (int s = 0; s < 2; s++) {
        char* st = sm + s * STG1;
        int adv = s * 128;
        #pragma unroll
        for (int t = 0; t < 4; t++) cp16(st + dA[t], srcA[t] + adv);
        cp16(st + dG, srcG + adv); cp16(st + dG + 32 * ROWB, srcG + BROW32 + adv);
        cp16(st + dU, srcU + adv); cp16(st + dU + 32 * ROWB, srcU + BROW32 + adv);
        cp_commit();
    }

    uint32_t sb = smem_u32(sm);
    int w = tid >> 5, lane = tid & 31;
    int wm = w >> 1, wn = w & 1;
    uint32_t aoff = (uint32_t)(wm * 32 + (lane & 15)) * ROWB + (lane >> 4) * 16u;
    uint32_t boff = (uint32_t)(wn * 32 + (lane & 7) + ((lane >> 4) << 3)) * ROWB
                    + ((lane >> 3) & 1) * 16u;

    float accg[2][4][4], accu[2][4][4];
    #pragma unroll
    for (int mt = 0; mt < 2; mt++)
        #pragma unroll
        for (int nt = 0; nt < 4; nt++)
            #pragma unroll
            for (int q = 0; q < 4; q++) { accg[mt][nt][q] = 0.f; accu[mt][nt][q] = 0.f; }

    const int T = HIDDEN / BKH;  // 16
    for (int j = 0; j < T; j++) {
        if (j < T - 1) cp_wait1(); else cp_wait0();
        __syncthreads();
        if (j + 2 < T) {
            char* st = sm + ((j + 2) % 3) * STG1;
            int adv = (j + 2) * 128;
            #pragma unroll
            for (int t = 0; t < 4; t++) cp16(st + dA[t], srcA[t] + adv);
            cp16(st + dG, srcG + adv); cp16(st + dG + 32 * ROWB, srcG + BROW32 + adv);
            cp16(st + dU, srcU + adv); cp16(st + dU + 32 * ROWB, srcU + BROW32 + adv);
            cp_commit();
        }
        uint32_t base = sb + (uint32_t)(j % 3) * STG1;
        #pragma unroll
        for (int kk = 0; kk < 4; kk++) {
            uint32_t a[2][4], bg[2][4], bu[2][4];
            ldsm4(a[0], base + aoff + kk * 32);
            ldsm4(a[1], base + aoff + 16 * ROWB + kk * 32);
            ldsm4(bg[0], base + 18432 + boff + kk * 32);
            ldsm4(bg[1], base + 18432 + boff + 16 * ROWB + kk * 32);
            ldsm4(bu[0], base + 27648 + boff + kk * 32);
            ldsm4(bu[1], base + 27648 + boff + 16 * ROWB + kk * 32);
            #pragma unroll
            for (int mt = 0; mt < 2; mt++)
                #pragma unroll
                for (int ng = 0; ng < 2; ng++)
                    #pragma unroll
                    for (int hh = 0; hh < 2; hh++) {
                        mma_f16(accg[mt][ng * 2 + hh], a[mt], &bg[ng][hh * 2]);
                        mma_f16(accu[mt][ng * 2 + hh], a[mt], &bu[ng][hh * 2]);
                    }
        }
    }

    #pragma unroll
    for (int mt = 0; mt < 2; mt++) {
        #pragma unroll
        for (int nt = 0; nt < 4; nt++) {
            int r0 = moff + wm * 32 + mt * 16 + (lane >> 2);
            int c  = n0 + wn * 32 + nt * 8 + 2 * (lane & 3);
            if (r0 < cnt) {
                __half* dst = g_act + (size_t)(off + r0) * INTER + c;
                float g0 = accg[mt][nt][0], u0 = accu[mt][nt][0];
                float g1 = accg[mt][nt][1], u1 = accu[mt][nt][1];
                *(__half2*)dst = __floats2half2_rn((g0 / (1.f + __expf(-g0))) * u0,
                                                   (g1 / (1.f + __expf(-g1))) * u1);
            }
            int r1 = r0 + 8;
            if (r1 < cnt) {
                __half* dst = g_act + (size_t)(off + r1) * INTER + c;
                float g0 = accg[mt][nt][2], u0 = accu[mt][nt][2];
                float g1 = accg[mt][nt][3], u1 = accu[mt][nt][3];
                *(__half2*)dst = __floats2half2_rn((g0 / (1.f + __expf(-g0))) * u0,
                                                   (g1 / (1.f + __expf(-g1))) * u1);
            }
        }
    }
}

// ---------------------------------------------------------------------------
// K6: GEMM2 (down) + fused weighted combine via atomicAdd.
//     BK=64, 4-stage pipeline, 2 blocks/SM.
// ---------------------------------------------------------------------------
__global__ void __launch_bounds__(256, 2)
k_ffn2(float* __restrict__ out, int e) {
    extern __shared__ __align__(16) char sm[];
    int cnt  = g_counts[e];
    int moff = blockIdx.x * BM;
    if (moff >= cnt) return;
    int off = g_offsets[e];
    int n0  = blockIdx.y * BN;
    int tid = threadIdx.x;

    int c16 = tid & 7;
    int rb  = tid >> 3;
    const char* srcA[4];
    uint32_t dA[4];
    #pragma unroll
    for (int t = 0; t < 4; t++) {
        int row = rb + 32 * t;
        dA[t] = (uint32_t)row * ROWB + c16 * 16u;
        int r = moff + row; if (r > cnt - 1) r = cnt - 1;
        srcA[t] = (const char*)(g_act + (size_t)(off + r) * INTER) + c16 * 16;
    }
    const char* srcB = (const char*)(g_dp_h + (size_t)e * HIDDEN * INTER +
                                     (size_t)(n0 + rb) * INTER) + c16 * 16;
    const uint32_t dB = 18432u + (uint32_t)rb * ROWB + c16 * 16u;
    const size_t BROW32 = (size_t)32 * INTER * 2;

    // prologue: stages 0,1,2
    #pragma unroll
    for (int s = 0; s < 3; s++) {
        char* st = sm + s * STG2;
        int adv = s * 128;
        #pragma unroll
        for (int t = 0; t < 4; t++) cp16(st + dA[t], srcA[t] + adv);
        cp16(st + dB, srcB + adv); cp16(st + dB + 32 * ROWB, srcB + BROW32 + adv);
        cp_commit();
    }

    uint32_t sb = smem_u32(sm);
    int w = tid >> 5, lane = tid & 31;
    int wm = w >> 1, wn = w & 1;
    uint32_t aoff = (uint32_t)(wm * 32 + (lane & 15)) * ROWB + (lane >> 4) * 16u;
    uint32_t boff = (uint32_t)(wn * 32 + (lane & 7) + ((lane >> 4) << 3)) * ROWB
                    + ((lane >> 3) & 1) * 16u;

    float acc[2][4][4];
    #pragma unroll
    for (int mt = 0; mt < 2; mt++)
        #pragma unroll
        for (int nt = 0; nt < 4; nt++)
            #pragma unroll
            for (int q = 0; q < 4; q++) acc[mt][nt][q] = 0.f;

    const int T = INTER / BKH;  // 44
    for (int j = 0; j < T; j++) {
        if (j < T - 2) cp_wait2();
        else if (j == T - 2) cp_wait1();
        else cp_wait0();
        __syncthreads();
        if (j + 3 < T) {
            char* st = sm + ((j + 3) & 3) * STG2;
            int adv = (j + 3) * 128;
            #pragma unroll
            for (int t = 0; t < 4; t++) cp16(st + dA[t], srcA[t] + adv);
            cp16(st + dB, srcB + adv); cp16(st + dB + 32 * ROWB, srcB + BROW32 + adv);
            cp_commit();
        }
        uint32_t base = sb + (uint32_t)(j & 3) * STG2;
        #pragma unroll
        for (int kk = 0; kk < 4; kk++) {
            uint32_t a[2][4], bb[2][4];
            ldsm4(a[0], base + aoff + kk * 32);
            ldsm4(a[1], base + aoff + 16 * ROWB + kk * 32);
            ldsm4(bb[0], base + 18432 + boff + kk * 32);
            ldsm4(bb[1], base + 18432 + boff + 16 * ROWB + kk * 32);
            #pragma unroll
            for (int mt = 0; mt < 2; mt++)
                #pragma unroll
                for (int ng = 0; ng < 2; ng++)
                    #pragma unroll
                    for (int hh = 0; hh < 2; hh++)
                        mma_f16(acc[mt][ng * 2 + hh], a[mt], &bb[ng][hh * 2]);
        }
    }

    #pragma unroll
    for (int mt = 0; mt < 2; mt++) {
        int r0 = moff + wm * 32 + mt * 16 + (lane >> 2);
        int r1 = r0 + 8;
        int   t0 = 0, t1 = 0;
        float w0 = 0.f, w1 = 0.f;
        bool ok0 = r0 < cnt, ok1 = r1 < cnt;
        if (ok0) { t0 = g_pair_token[off + r0]; w0 = g_pair_w[off + r0]; }
        if (ok1) { t1 = g_pair_token[off + r1]; w1 = g_pair_w[off + r1]; }
        #pragma unroll
        for (int nt = 0; nt < 4; nt++) {
            int c = n0 + wn * 32 + nt * 8 + 2 * (lane & 3);
            if (ok0) {
                float* dst = out + (size_t)t0 * HIDDEN + c;
                atomicAdd(dst + 0, w0 * acc[mt][nt][0]);
                atomicAdd(dst + 1, w0 * acc[mt][nt][1]);
            }
            if (ok1) {
                float* dst = out + (size_t)t1 * HIDDEN + c;
                atomicAdd(dst + 0, w1 * acc[mt][nt][2]);
                atomicAdd(dst + 1, w1 * acc[mt][nt][3]);
            }
        }
    }
}

// ---------------------------------------------------------------------------
extern "C" void kernel_launch(void* const* d_in, const int* in_sizes, int n_in,
                              void* d_out, int out_size) {
    const float* hs   = (const float*)d_in[0];
    const int*   tid  = (const int*)d_in[1];
    const float* temb = (const float*)d_in[2];
    const float* trw  = (const float*)d_in[3];
    const float* gw   = (const float*)d_in[4];
    const float* gp   = (const float*)d_in[5];
    const float* up   = (const float*)d_in[6];
    const float* dp   = (const float*)d_in[7];
    float* out = (float*)d_out;

    cudaFuncSetAttribute(k_ffn1, cudaFuncAttributeMaxDynamicSharedMemorySize, SMEM1);
    cudaFuncSetAttribute(k_ffn2, cudaFuncAttributeMaxDynamicSharedMemorySize, SMEM2);

    __half* gph; __half* uph; __half* dph;
    cudaGetSymbolAddress((void**)&gph, g_gp_h);
    cudaGetSymbolAddress((void**)&uph, g_up_h);
    cudaGetSymbolAddress((void**)&dph, g_dp_h);

    // route on default stream; everything depends on it
    k_task_route<<<1, 256>>>(temb, tid, trw);
    cudaEventRecord(ev_route, 0);

    // gating chain on default stream (concurrent with per-expert cvts)
    k_gate<<<NTOK / 8, 256>>>(hs, temb, tid, gw, out);
    k_prefix<<<1, 32>>>();
    k_place<<<NTOK / 256, 256>>>();
    cudaEventRecord(ev_prep, 0);

    dim3 gc(256, 3);                  // per-expert cvt: 3 tensors
    dim3 g1(NTOK / BM, INTER / BN);   // 64 x 44
    dim3 g2(NTOK / BM, HIDDEN / BN);  // 64 x 16

    // experts 4..7 weights convert on side stream (hidden under first GEMM wave)
    cudaStreamWaitEvent(s_cvt, ev_route, 0);
    for (int e = 4; e < 8; e++)
        k_cvt_e<<<gc, 256, 0, s_cvt>>>((const float4*)gp, (const float4*)up, (const float4*)dp,
                                       (uint4*)gph, (uint4*)uph, (uint4*)dph, e);
    cudaEventRecord(ev_cvt, s_cvt);

    // per-expert chains: stream i handles experts i and i+4
    for (int i = 0; i < 4; i++) {
        cudaStreamWaitEvent(s_exp[i], ev_route, 0);
        k_cvt_e<<<gc, 256, 0, s_exp[i]>>>((const float4*)gp, (const float4*)up, (const float4*)dp,
                                          (uint4*)gph, (uint4*)uph, (uint4*)dph, i);
        cudaStreamWaitEvent(s_exp[i], ev_prep, 0);
        k_ffn1<<<g1, 256, SMEM1, s_exp[i]>>>(i);
        k_ffn2<<<g2, 256, SMEM2, s_exp[i]>>>(out, i);
        cudaStreamWaitEvent(s_exp[i], ev_cvt, 0);
        k_ffn1<<<g1, 256, SMEM1, s_exp[i]>>>(i + 4);
        k_ffn2<<<g2, 256, SMEM2, s_exp[i]>>>(out, i + 4);
        cudaEventRecord(ev_done[i], s_exp[i]);
    }
    for (int i = 0; i < 4; i++)
        cudaStreamWaitEvent(0, ev_done[i], 0);
}